// round 7
// baseline (speedup 1.0000x reference)
#include <cuda_runtime.h>
#include <cstdint>
#include <math_constants.h>

// Problem constants (fixed by the reference: M=4 molecules, N=2048 atoms)
#define NATOMS  2048
#define NMOL    4
#define NPAIRU  2096128u                        // N*(N-1)/2
#define MPU     (4u * NPAIRU)                   // 8,384,512  (6*MPU < 2^31)

// Output layout (flattened concat of the reference tuple, float32):
//   [0,     2*MP) : atom_index12 ([2, M*P] row-major, as float)
//   [2*MP,  5*MP) : shift_values ([M*P, 3], all zeros)  <- dedicated zero blocks
//   [5*MP,  6*MP) : mask         ([M*P], 1.0/0.0)

// Scratch: coords packed as float4 per atom, NaN-filled where species == -1.
__device__ float4 g_c4[NMOL * NATOMS];

__device__ __forceinline__ int row_offset(int i) {
    // offset of row i in triu_indices(N, k=1): i*(2N-1-i)/2
    return (i * (2 * NATOMS - 1 - i)) >> 1;
}

__global__ void prep_kernel(const int*   __restrict__ species,
                            const float* __restrict__ coords)
{
    const int a = blockIdx.x * blockDim.x + threadIdx.x;   // 0 .. NMOL*NATOMS-1
    float x = coords[3 * a + 0];
    float y = coords[3 * a + 1];
    float z = coords[3 * a + 2];
    if (species[a] == -1) { x = CUDART_NAN_F; y = CUDART_NAN_F; z = CUDART_NAN_F; }
    g_c4[a] = make_float4(x, y, z, 0.0f);
}

__device__ __forceinline__ void invert_tri(int p, int& i, int& j) {
    // disc = 4095^2 - 8p < 2^24 -> exact fp32; sqrtf est fixed up to exactness.
    const int disc = 16769025 - 8 * p;
    int ii = (int)((4095.0f - sqrtf((float)disc)) * 0.5f);
    if (ii < 0) ii = 0;
    while (row_offset(ii + 1) <= p) ++ii;
    while (row_offset(ii) > p)      --ii;
    i = ii;
    j = ii + 1 + (p - row_offset(ii));
}

// Heterogeneous grid: 10235 blocks = 5 * 2047.
//   bid % 5 == 4 -> zero block  (zid = bid/5, 0..2046): pure STG.128 stream
//   bid % 5 <  4 -> pair block  (pid = (bid/5)*4 + bid%5, 0..8187)
__global__ __launch_bounds__(256)
void fullpairwise_kernel(float* __restrict__ out)
{
    const unsigned bid = blockIdx.x;
    const unsigned g   = bid / 5u;
    const unsigned r   = bid - 5u * g;
    const unsigned tid = threadIdx.x;

    if (r == 4u) {
        // ---- zero block: fill 3072 float4 of the shift_values region ----
        // region = [2*MP, 5*MP) floats = 6,288,384 float4 = 2047 * 3072.
        float4* zp = reinterpret_cast<float4*>(out + 2u * MPU) + g * 3072u;
        const float4 z4 = make_float4(0.f, 0.f, 0.f, 0.f);
        #pragma unroll
        for (int u = 0; u < 12; ++u)
            zp[tid + 256u * u] = z4;
        return;
    }

    // ---- pair block ----
    const unsigned pid = g * 4u + r;             // 0..8187
    const int      m   = (int)(pid & 3u);        // molecule
    const unsigned b   = pid >> 2;               // 0..2046 block-within-molecule
    const unsigned p0  = b * 1024u + tid;        // pair id for k=0 (exact cover)

    const float4* __restrict__ cm = g_c4 + m * NATOMS;
    const float    cut2 = 5.2f * 5.2f;           // fp32, matches jnp
    const float    foff = (float)(m * NATOMS);
    const unsigned qm   = (unsigned)m * NPAIRU;

    int i, j;
    invert_tri((int)p0, i, j);

    #pragma unroll
    for (int k = 0; k < 4; ++k) {
        const float4 ci = __ldg(&cm[i]);   // warp-uniform-ish broadcast
        const float4 cj = __ldg(&cm[j]);   // lane-consecutive -> coalesced

        const float dx = ci.x - cj.x;
        const float dy = ci.y - cj.y;
        const float dz = ci.z - cj.z;
        // exact fp32, no FMA contraction, jnp reduction order ((x^2+y^2)+z^2);
        // NaN (padded atoms) compares false, matching the reference mask.
        const float d2 = __fadd_rn(__fadd_rn(__fmul_rn(dx, dx),
                                             __fmul_rn(dy, dy)),
                                   __fmul_rn(dz, dz));

        const unsigned q = qm + p0 + (unsigned)k * 256u;
        out[q]            = (float)i + foff;          // atom_index12 row 0
        out[MPU + q]      = (float)j + foff;          // atom_index12 row 1
        out[5u * MPU + q] = (d2 <= cut2) ? 1.f : 0.f; // mask

        if (k < 3) {
            j += 256;
            if (j >= NATOMS) {
                // crossed >=1 row boundary; rare wrap-heavy tail -> recompute
                invert_tri((int)(p0 + (unsigned)(k + 1) * 256u), i, j);
            }
        }
    }
}

extern "C" void kernel_launch(void* const* d_in, const int* in_sizes, int n_in,
                              void* d_out, int out_size)
{
    const int*   species = (const int*)  d_in[0];
    const float* coords  = (const float*)d_in[1];
    float*       out     = (float*)d_out;

    prep_kernel<<<(NMOL * NATOMS) / 256, 256>>>(species, coords);
    fullpairwise_kernel<<<10235, 256>>>(out);   // 8188 pair + 2047 zero blocks
}

// round 9
// speedup vs baseline: 1.4325x; 1.4325x over previous
#include <cuda_runtime.h>
#include <cstdint>
#include <math_constants.h>

// Problem constants (fixed by the reference: M=4 molecules, N=2048 atoms)
#define NATOMS  2048
#define NMOL    4
#define NPAIRU  2096128u                        // N*(N-1)/2
#define MPU     (4u * NPAIRU)                   // 8,384,512  (6*MPU < 2^31)

// Output layout (flattened concat of the reference tuple, float32):
//   [0,     2*MP) : atom_index12 ([2, M*P] row-major, as float)
//   [2*MP,  5*MP) : shift_values ([M*P, 3], all zeros, fused into pair blocks)
//   [5*MP,  6*MP) : mask         ([M*P], 1.0/0.0)

// Scratch: coords packed as float4 per atom, NaN-filled where species == -1.
__device__ float4 g_c4[NMOL * NATOMS];

__device__ __forceinline__ int row_offset(int i) {
    // offset of row i in triu_indices(N, k=1): i*(2N-1-i)/2
    return (i * (2 * NATOMS - 1 - i)) >> 1;
}

__global__ void prep_kernel(const int*   __restrict__ species,
                            const float* __restrict__ coords)
{
    const int a = blockIdx.x * blockDim.x + threadIdx.x;   // 0 .. NMOL*NATOMS-1
    float x = coords[3 * a + 0];
    float y = coords[3 * a + 1];
    float z = coords[3 * a + 2];
    if (species[a] == -1) { x = CUDART_NAN_F; y = CUDART_NAN_F; z = CUDART_NAN_F; }
    g_c4[a] = make_float4(x, y, z, 0.0f);
}

__device__ __forceinline__ void invert_tri(int p, int& i, int& j) {
    // disc = 4095^2 - 8p < 2^24 -> exact fp32; sqrtf est fixed up to exactness.
    const int disc = 16769025 - 8 * p;
    int ii = (int)((4095.0f - sqrtf((float)disc)) * 0.5f);
    if (ii < 0) ii = 0;
    while (row_offset(ii + 1) <= p) ++ii;
    while (row_offset(ii) > p)      --ii;
    i = ii;
    j = ii + 1 + (p - row_offset(ii));
}

__global__ __launch_bounds__(256)
void fullpairwise_kernel(float* __restrict__ out)
{
    const int      m   = blockIdx.y;
    const unsigned tid = threadIdx.x;
    const unsigned p0  = blockIdx.x * 1024u + tid;   // pair id for k=0
    // grid.x = NPAIR/1024 = 2047 exactly -> no bounds checks

    const float4* __restrict__ cm = g_c4 + m * NATOMS;
    const float    cut2 = 5.2f * 5.2f;               // fp32, matches jnp
    const float    foff = (float)(m * NATOMS);
    const unsigned qm   = (unsigned)m * NPAIRU;

    // ---- zeros region (fused): flat fill, coalesced STG.128 ----
    {
        const unsigned zoff = 2u * MPU + 3u * (qm + blockIdx.x * 1024u);
        float4* zp = reinterpret_cast<float4*>(out + zoff);   // 768 float4/block
        const float4 z4 = make_float4(0.f, 0.f, 0.f, 0.f);
        zp[tid]        = z4;
        zp[tid + 256u] = z4;
        zp[tid + 512u] = z4;
    }

    // ---- invert triangular index ONCE (k=0) ----
    int i, j;
    invert_tri((int)p0, i, j);

    // ---- 4 pairs per thread, 256 apart: coalesced loads & scalar stores ----
    #pragma unroll
    for (int k = 0; k < 4; ++k) {
        const float4 ci = __ldg(&cm[i]);   // warp-uniform-ish broadcast
        const float4 cj = __ldg(&cm[j]);   // lane-consecutive -> coalesced

        const float dx = ci.x - cj.x;
        const float dy = ci.y - cj.y;
        const float dz = ci.z - cj.z;
        // exact fp32, no FMA contraction, jnp reduction order ((x^2+y^2)+z^2);
        // NaN (padded atoms) compares false, matching the reference mask.
        const float d2 = __fadd_rn(__fadd_rn(__fmul_rn(dx, dx),
                                             __fmul_rn(dy, dy)),
                                   __fmul_rn(dz, dz));

        const unsigned q = qm + p0 + (unsigned)k * 256u;
        out[q]            = (float)i + foff;          // atom_index12 row 0
        out[MPU + q]      = (float)j + foff;          // atom_index12 row 1
        out[5u * MPU + q] = (d2 <= cut2) ? 1.f : 0.f; // mask

        // advance 256 pairs; rare row-crossing handled by exact recompute
        if (k < 3) {
            j += 256;
            if (j >= NATOMS)
                invert_tri((int)(p0 + (unsigned)(k + 1) * 256u), i, j);
        }
    }
}

extern "C" void kernel_launch(void* const* d_in, const int* in_sizes, int n_in,
                              void* d_out, int out_size)
{
    const int*   species = (const int*)  d_in[0];
    const float* coords  = (const float*)d_in[1];
    float*       out     = (float*)d_out;

    prep_kernel<<<(NMOL * NATOMS) / 256, 256>>>(species, coords);

    dim3 grid(NPAIRU / 1024u, NMOL);   // (2047, 4), exact coverage
    fullpairwise_kernel<<<grid, 256>>>(out);
}

// round 10
// speedup vs baseline: 1.4900x; 1.0401x over previous
#include <cuda_runtime.h>
#include <cstdint>
#include <math_constants.h>

// Problem constants (fixed by the reference: M=4 molecules, N=2048 atoms)
#define NATOMS  2048
#define NMOL    4
#define NPAIRU  2096128u                        // N*(N-1)/2
#define MPU     (4u * NPAIRU)                   // 8,384,512  (6*MPU < 2^31)

// Output layout (flattened concat of the reference tuple, float32):
//   [0,     2*MP) : atom_index12 ([2, M*P] row-major, as float)
//   [2*MP,  5*MP) : shift_values ([M*P, 3], all zeros, fused)
//   [5*MP,  6*MP) : mask         ([M*P], 1.0/0.0)

// Scratch: coords packed as float4 per atom, NaN-filled where species == -1.
__device__ float4 g_c4[NMOL * NATOMS];

__device__ __forceinline__ int row_offset(int i) {
    // offset of row i in triu_indices(N, k=1): i*(2N-1-i)/2
    return (i * (2 * NATOMS - 1 - i)) >> 1;
}

__global__ void prep_kernel(const int*   __restrict__ species,
                            const float* __restrict__ coords)
{
    const int a = blockIdx.x * blockDim.x + threadIdx.x;   // 0 .. NMOL*NATOMS-1
    float x = coords[3 * a + 0];
    float y = coords[3 * a + 1];
    float z = coords[3 * a + 2];
    if (species[a] == -1) { x = CUDART_NAN_F; y = CUDART_NAN_F; z = CUDART_NAN_F; }
    g_c4[a] = make_float4(x, y, z, 0.0f);
}

__device__ __forceinline__ void invert_tri(int p, int& i, int& j) {
    // disc = 4095^2 - 8p < 2^24 -> exact fp32; sqrtf est fixed up to exactness.
    const int disc = 16769025 - 8 * p;
    int ii = (int)((4095.0f - sqrtf((float)disc)) * 0.5f);
    if (ii < 0) ii = 0;
    while (row_offset(ii + 1) <= p) ++ii;
    while (row_offset(ii) > p)      --ii;
    i = ii;
    j = ii + 1 + (p - row_offset(ii));
}

__global__ __launch_bounds__(256)
void fullpairwise_kernel(float* __restrict__ out)
{
    const int      m   = blockIdx.y;
    const unsigned tid = threadIdx.x;
    const unsigned p0  = blockIdx.x * 1024u + tid;   // pair id for k=0
    // grid.x = NPAIR/1024 = 2047 exactly -> no bounds checks

    const float4* __restrict__ cm = g_c4 + m * NATOMS;
    const float    cut2 = 5.2f * 5.2f;               // fp32, matches jnp
    const float    foff = (float)(m * NATOMS);
    const unsigned qm   = (unsigned)m * NPAIRU;

    // ---- zeros region (fused): flat fill, coalesced STG.128, evict-first ----
    {
        const unsigned zoff = 2u * MPU + 3u * (qm + blockIdx.x * 1024u);
        float4* zp = reinterpret_cast<float4*>(out + zoff);   // 768 float4/block
        const float4 z4 = make_float4(0.f, 0.f, 0.f, 0.f);
        __stcs(zp + tid,        z4);
        __stcs(zp + tid + 256u, z4);
        __stcs(zp + tid + 512u, z4);
    }

    // ---- invert triangular index ONCE (k=0) ----
    int i, j;
    invert_tri((int)p0, i, j);

    // ---- 4 pairs per thread, 256 apart: coalesced loads & scalar stores ----
    #pragma unroll
    for (int k = 0; k < 4; ++k) {
        const float4 ci = __ldg(&cm[i]);   // warp-uniform-ish broadcast
        const float4 cj = __ldg(&cm[j]);   // lane-consecutive -> coalesced

        const float dx = ci.x - cj.x;
        const float dy = ci.y - cj.y;
        const float dz = ci.z - cj.z;
        // exact fp32, no FMA contraction, jnp reduction order ((x^2+y^2)+z^2);
        // NaN (padded atoms) compares false, matching the reference mask.
        const float d2 = __fadd_rn(__fadd_rn(__fmul_rn(dx, dx),
                                             __fmul_rn(dy, dy)),
                                   __fmul_rn(dz, dz));

        const unsigned q = qm + p0 + (unsigned)k * 256u;
        __stcs(out + q,            (float)i + foff);           // idx row 0
        __stcs(out + MPU + q,      (float)j + foff);           // idx row 1
        __stcs(out + 5u * MPU + q, (d2 <= cut2) ? 1.f : 0.f);  // mask

        // advance 256 pairs; rare row-crossing handled by exact recompute
        if (k < 3) {
            j += 256;
            if (j >= NATOMS)
                invert_tri((int)(p0 + (unsigned)(k + 1) * 256u), i, j);
        }
    }
}

extern "C" void kernel_launch(void* const* d_in, const int* in_sizes, int n_in,
                              void* d_out, int out_size)
{
    const int*   species = (const int*)  d_in[0];
    const float* coords  = (const float*)d_in[1];
    float*       out     = (float*)d_out;

    prep_kernel<<<(NMOL * NATOMS) / 128, 128>>>(species, coords);

    dim3 grid(NPAIRU / 1024u, NMOL);   // (2047, 4), exact coverage
    fullpairwise_kernel<<<grid, 256>>>(out);
}